// round 16
// baseline (speedup 1.0000x reference)
#include <cuda_runtime.h>
#include <cuda_fp16.h>
#include <math.h>
#include <stdint.h>

// Problem constants
#define BSZ 4
#define TT  4096
#define DD  2048
#define MR  (BSZ * TT)      // 16384 rows
#define LCH 32              // scan chunk length
#define NCH (TT / LCH)      // 128 chunks
#define ELEMS (MR * DD)

// ---------------- scratch (device globals; no allocation allowed) ----------
__device__ __half g_i16[ELEMS];                   // si = swish(i_raw)  fp16
__device__ __half g_f16[ELEMS];                   // a  = sigmoid(f_raw) fp16
__device__ __half g_g16[ELEMS];                   // gsw = swish(g_raw) fp16
__device__ float  g_P[BSZ * NCH * DD];
__device__ float  g_S[BSZ * NCH * DD];
__device__ float  g_H[BSZ * NCH * DD];
__device__ __half g_abuf[(size_t)MR * DD];        // fp16 activations (x, then y)
__device__ __half g_wbuf[(size_t)8192 * DD];      // [Wi|Wf|Wg|Wo] fp16, K-major

// =================== PTX helpers ===========================================
__device__ __forceinline__ uint32_t smem_u32(const void* p) {
    uint32_t a;
    asm("{ .reg .u64 t; cvta.to.shared.u64 t, %1; cvt.u32.u64 %0, t; }" : "=r"(a) : "l"(p));
    return a;
}
__device__ __forceinline__ void cp_async16(uint32_t dst, const void* src) {
    asm volatile("cp.async.cg.shared.global [%0], [%1], 16;" :: "r"(dst), "l"(src) : "memory");
}
__device__ __forceinline__ void cp_commit() {
    asm volatile("cp.async.commit_group;" ::: "memory");
}
template <int N>
__device__ __forceinline__ void cp_wait() {
    asm volatile("cp.async.wait_group %0;" :: "n"(N) : "memory");
}
__device__ __forceinline__ void ldm_x4(uint32_t* r, uint32_t addr) {
    asm volatile("ldmatrix.sync.aligned.m8n8.x4.shared.b16 {%0,%1,%2,%3}, [%4];"
        : "=r"(r[0]), "=r"(r[1]), "=r"(r[2]), "=r"(r[3]) : "r"(addr));
}
__device__ __forceinline__ void mma16816(float* c, const uint32_t* a, const uint32_t* b) {
    asm volatile("mma.sync.aligned.m16n8k16.row.col.f32.f16.f16.f32 "
        "{%0,%1,%2,%3}, {%4,%5,%6,%7}, {%8,%9}, {%0,%1,%2,%3};"
        : "+f"(c[0]), "+f"(c[1]), "+f"(c[2]), "+f"(c[3])
        : "r"(a[0]), "r"(a[1]), "r"(a[2]), "r"(a[3]), "r"(b[0]), "r"(b[1]));
}

// typed pair-stores for the GEMM epilogue
__device__ __forceinline__ void store2(float* p, float a, float b) {
    float2 v; v.x = a; v.y = b; *(float2*)p = v;
}
__device__ __forceinline__ void store2(__half* p, float a, float b) {
    __half2 v; v.x = __float2half(a); v.y = __float2half(b); *(__half2*)p = v;
}

// fp16x4 <-> fp32x4
__device__ __forceinline__ float4 h4_to_f4(uint2 v) {
    __half2 lo = *reinterpret_cast<__half2*>(&v.x);
    __half2 hi = *reinterpret_cast<__half2*>(&v.y);
    float2 f01 = __half22float2(lo);
    float2 f23 = __half22float2(hi);
    return make_float4(f01.x, f01.y, f23.x, f23.y);
}
__device__ __forceinline__ uint2 f4_to_h4(float4 v) {
    __half2 lo; lo.x = __float2half(v.x); lo.y = __float2half(v.y);
    __half2 hi; hi.x = __float2half(v.z); hi.y = __float2half(v.w);
    uint2 r;
    r.x = *reinterpret_cast<uint32_t*>(&lo);
    r.y = *reinterpret_cast<uint32_t*>(&hi);
    return r;
}

// fast sigmoid / swish (MUFU.RCP based)
__device__ __forceinline__ float fsig(float x) {
    return __fdividef(1.f, 1.f + __expf(-x));
}
__device__ __forceinline__ float fswish(float x) {
    return x * fsig(x);
}

// =================== conversions ===========================================
// activations: fp32 [M, 2048] -> plain fp16 [M, 2048]
__global__ __launch_bounds__(256)
void convert_act_kernel(const float* __restrict__ in, __half* __restrict__ out) {
    size_t idx = ((size_t)blockIdx.x * blockDim.x + threadIdx.x) * 4;
    float4 v = *(const float4*)(in + idx);
    __half2 h0; h0.x = __float2half(v.x); h0.y = __float2half(v.y);
    __half2 h1; h1.x = __float2half(v.z); h1.y = __float2half(v.w);
    *(__half2*)(out + idx) = h0;
    *(__half2*)(out + idx + 2) = h1;
}

// weights: fp32 W[k, n] -> fp16 Bo[n + 2048*z, 2048] K-major; one launch, z picks W
__global__ __launch_bounds__(256)
void convert_w_kernel(const float* __restrict__ W0, const float* __restrict__ W1,
                      const float* __restrict__ W2, const float* __restrict__ W3,
                      __half* __restrict__ Bo) {
    const float* Wsel[4] = {W0, W1, W2, W3};
    const float* W = Wsel[blockIdx.z];
    __half* B = Bo + (size_t)blockIdx.z * 2048 * DD;
    __shared__ float ts[32][33];
    int n0 = blockIdx.x * 32, k0 = blockIdx.y * 32;
    int tx = threadIdx.x, ty = threadIdx.y;  // (32, 8)
#pragma unroll
    for (int i = 0; i < 4; i++)
        ts[ty + i * 8][tx] = W[(size_t)(k0 + ty + i * 8) * DD + n0 + tx];
    __syncthreads();
#pragma unroll
    for (int i = 0; i < 4; i++) {
        int n = n0 + ty + i * 8;
        float v = ts[tx][ty + i * 8];     // = W[k0+tx][n]
        B[(size_t)n * DD + k0 + tx] = __float2half(v);
    }
}

// =================== mma.sync fp16 GEMM (R12 config — FROZEN mainloop) =====
// MODE 0: plain store. MODE 1: gate epilogue — which==1 stores sigmoid(acc),
// which==0/2 store swish(acc).
#define BM 128
#define BN 128
#define BKE 32
#define STAGE_A (BM * BKE * 2)              // 8192 B
#define STAGE_B (BN * BKE * 2)              // 8192 B
#define STAGE_BYTES (STAGE_A + STAGE_B)     // 16384
#define GEMM_SMEM (4 * STAGE_BYTES)         // 64 KB
#define KTILES (DD / BKE)                   // 64

// swizzled smem offset for a 16B chunk: row has 4 chunks (64B)
__device__ __forceinline__ uint32_t swz(int row, int ch) {
    return (uint32_t)(row * 64 + ((ch ^ ((row >> 1) & 3)) << 4));
}

template <typename TO, int MODE>
__global__ __launch_bounds__(256)
void gemm_mma_kernel(const __half* __restrict__ A, const __half* __restrict__ B,
                     TO* __restrict__ C0, TO* __restrict__ C1,
                     TO* __restrict__ C2) {
    extern __shared__ char smem[];
    const uint32_t sb = smem_u32(smem);
    const int tid = threadIdx.x;
    const int lane = tid & 31;
    const int wid = tid >> 5;
    const int wm = wid & 1;       // 2 warps over M: 64 rows each
    const int wn = wid >> 1;      // 4 warps over N: 32 cols each

    const __half* gA = A + (size_t)blockIdx.y * BM * DD;
    const __half* gB = B + (size_t)blockIdx.x * BN * DD;

    uint32_t aof[2][4], bof[2][2];
#pragma unroll
    for (int ks = 0; ks < 2; ks++) {
#pragma unroll
        for (int mf = 0; mf < 4; mf++) {
            int r = wm * 64 + mf * 16 + (lane & 15);
            int ch = ks * 2 + (lane >> 4);
            aof[ks][mf] = swz(r, ch);
        }
#pragma unroll
        for (int p = 0; p < 2; p++) {
            int r = wn * 32 + p * 16 + (lane & 7) + ((lane >> 4) << 3);
            int ch = ks * 2 + ((lane >> 3) & 1);
            bof[ks][p] = STAGE_A + swz(r, ch);
        }
    }

    float acc[4][4][4];
#pragma unroll
    for (int i = 0; i < 4; i++)
#pragma unroll
        for (int j = 0; j < 4; j++)
#pragma unroll
            for (int q = 0; q < 4; q++) acc[i][j][q] = 0.f;

    auto load_tile = [&](int kt) {
        uint32_t st = sb + (uint32_t)(kt & 3) * STAGE_BYTES;
        size_t koff = (size_t)kt * BKE;
#pragma unroll
        for (int h = 0; h < 2; h++) {
            int id = tid + h * 256;
            int row = id >> 2, ch = id & 3;
            cp_async16(st + swz(row, ch), gA + (size_t)row * DD + koff + ch * 8);
        }
#pragma unroll
        for (int h = 0; h < 2; h++) {
            int id = tid + h * 256;
            int row = id >> 2, ch = id & 3;
            cp_async16(st + STAGE_A + swz(row, ch), gB + (size_t)row * DD + koff + ch * 8);
        }
    };

    load_tile(0); cp_commit();
    load_tile(1); cp_commit();
    load_tile(2); cp_commit();

#pragma unroll 1
    for (int kt = 0; kt < KTILES; ++kt) {
        cp_wait<2>();
        __syncthreads();
        if (kt + 3 < KTILES) load_tile(kt + 3);
        cp_commit();

        uint32_t st = sb + (uint32_t)(kt & 3) * STAGE_BYTES;
#pragma unroll
        for (int ks = 0; ks < 2; ks++) {
            uint32_t ar[4][4], br[2][4];
#pragma unroll
            for (int mf = 0; mf < 4; mf++) ldm_x4(ar[mf], st + aof[ks][mf]);
#pragma unroll
            for (int p = 0; p < 2; p++) ldm_x4(br[p], st + bof[ks][p]);
#pragma unroll
            for (int mf = 0; mf < 4; mf++)
#pragma unroll
                for (int nf = 0; nf < 4; nf++)
                    mma16816(acc[mf][nf], ar[mf], &br[nf >> 1][(nf & 1) * 2]);
        }
    }

    // epilogue: pick output by weight block (blockIdx.x >> 4); optional gate
    int which = blockIdx.x >> 4;
    TO* Cb = (which == 0) ? C0 : (which == 1) ? C1 : C2;
    int colbase = (blockIdx.x & 15) * BN;
    auto actf = [&](float v) -> float {
        if (MODE == 0) return v;
        return (which == 1) ? fsig(v) : fswish(v);
    };
#pragma unroll
    for (int mf = 0; mf < 4; mf++) {
#pragma unroll
        for (int nf = 0; nf < 4; nf++) {
            int row = blockIdx.y * BM + wm * 64 + mf * 16 + (lane >> 2);
            int col = colbase + wn * 32 + nf * 8 + (lane & 3) * 2;
            store2(Cb + (size_t)row * DD + col, actf(acc[mf][nf][0]), actf(acc[mf][nf][1]));
            store2(Cb + (size_t)(row + 8) * DD + col, actf(acc[mf][nf][2]), actf(acc[mf][nf][3]));
        }
    }
}

// ---------------- scan pass1 (gates precomputed; pure fma streaming) -------
#define D4 (DD / 4)

__global__ void scan_pass1_kernel(const __half* __restrict__ ab, const __half* __restrict__ sib,
                                  float* __restrict__ P, float* __restrict__ S) {
    int idx = blockIdx.x * blockDim.x + threadIdx.x;   // over BSZ*NCH*D4
    int d4 = idx % D4;
    int c = (idx / D4) % NCH;
    int b = idx / (D4 * NCH);
    size_t base4 = (((size_t)(b * TT + c * LCH)) * DD) / 4 + d4;
    const uint2* a4 = (const uint2*)ab;
    const uint2* s4 = (const uint2*)sib;
    float4 h = make_float4(0.f, 0.f, 0.f, 0.f);
    float4 p = make_float4(1.f, 1.f, 1.f, 1.f);
#pragma unroll 4
    for (int j = 0; j < LCH; j++) {
        float4 a = h4_to_f4(a4[base4 + (size_t)j * D4]);
        float4 si = h4_to_f4(s4[base4 + (size_t)j * D4]);
        h.x = fmaf(a.x, h.x - si.x, si.x); p.x *= a.x;   // a*h + si*(1-a)
        h.y = fmaf(a.y, h.y - si.y, si.y); p.y *= a.y;
        h.z = fmaf(a.z, h.z - si.z, si.z); p.z *= a.z;
        h.w = fmaf(a.w, h.w - si.w, si.w); p.w *= a.w;
    }
    ((float4*)P)[idx] = p;
    ((float4*)S)[idx] = h;
}

// pass2: scalar, one thread per (b, d) column
__global__ void scan_pass2_kernel(const float* __restrict__ P, const float* __restrict__ S,
                                  float* __restrict__ H) {
    int idx = blockIdx.x * blockDim.x + threadIdx.x;   // over BSZ*DD
    int d = idx % DD;
    int b = idx / DD;
    float h = 0.f;
#pragma unroll 4
    for (int c = 0; c < NCH; c++) {
        int s = (b * NCH + c) * DD + d;
        H[s] = h;
        h = fmaf(P[s], h, S[s]);
    }
}

// ---------------- fused pass3 + RMSNorm + gate + fp16 convert --------------
// One block = one (b, chunk): 512 threads cover the full d-range (D4=512).
// Per time step: scan update, block-wide sumsq reduction, scale, write y.
__global__ __launch_bounds__(512)
void scan3_norm_kernel(const __half* __restrict__ ab, const __half* __restrict__ sib,
                       const float* __restrict__ H, const __half* __restrict__ gsw,
                       const float* __restrict__ gw, __half* __restrict__ out) {
    const int blk = blockIdx.x;          // over BSZ*NCH
    const int c = blk % NCH;
    const int b = blk / NCH;
    const int tid = threadIdx.x;         // d4 index, 0..511
    const int lane = tid & 31;
    const int wrp = tid >> 5;            // 0..15
    __shared__ float wsum[2][16];

    const size_t base4 = ((size_t)(b * TT + c * LCH)) * D4 + tid;
    const uint2* a4 = (const uint2*)ab;
    const uint2* s4 = (const uint2*)sib;
    const uint2* g4 = (const uint2*)gsw;
    uint2* y4 = (uint2*)out;

    float4 h = ((const float4*)H)[(size_t)blk * D4 + tid];
    const float4 w = ((const float4*)gw)[tid];

    // prefetch step 0
    uint2 a_pre = a4[base4];
    uint2 s_pre = s4[base4];
    uint2 g_pre = g4[base4];

#pragma unroll 1
    for (int j = 0; j < LCH; j++) {
        float4 a = h4_to_f4(a_pre);
        float4 si = h4_to_f4(s_pre);
        float4 gv = h4_to_f4(g_pre);
        if (j + 1 < LCH) {
            size_t nb = base4 + (size_t)(j + 1) * D4;
            a_pre = a4[nb];
            s_pre = s4[nb];
            g_pre = g4[nb];
        }
        h.x = fmaf(a.x, h.x - si.x, si.x);
        h.y = fmaf(a.y, h.y - si.y, si.y);
        h.z = fmaf(a.z, h.z - si.z, si.z);
        h.w = fmaf(a.w, h.w - si.w, si.w);

        float ss = fmaf(h.x, h.x, fmaf(h.y, h.y, fmaf(h.z, h.z, h.w * h.w)));
#pragma unroll
        for (int o = 16; o > 0; o >>= 1)
            ss += __shfl_xor_sync(0xffffffffu, ss, o);
        if (lane == 0) wsum[j & 1][wrp] = ss;
        __syncthreads();
        float tot = 0.f;
#pragma unroll
        for (int q = 0; q < 16; q++) tot += wsum[j & 1][q];
        float rinv = rsqrtf(tot * (1.f / (float)DD) + 1e-5f);

        float4 y;
        y.x = (h.x * rinv * w.x) * gv.x;
        y.y = (h.y * rinv * w.y) * gv.y;
        y.z = (h.z * rinv * w.z) * gv.z;
        y.w = (h.w * rinv * w.w) * gv.w;
        y4[base4 + (size_t)j * D4] = f4_to_h4(y);
    }
}

// ---------------- launch ----------------------------------------------------
extern "C" void kernel_launch(void* const* d_in, const int* in_sizes, int n_in,
                              void* d_out, int out_size) {
    const float* x  = (const float*)d_in[0];
    const float* Wi = (const float*)d_in[1];
    const float* Wf = (const float*)d_in[2];
    const float* Wg = (const float*)d_in[3];
    const float* Wo = (const float*)d_in[4];
    const float* gw = (const float*)d_in[5];
    float* out = (float*)d_out;

    float *p_P, *p_S, *p_H;
    __half *p_i16, *p_f16, *p_g16, *p_abuf, *p_wbuf;
    cudaGetSymbolAddress((void**)&p_i16, g_i16);
    cudaGetSymbolAddress((void**)&p_f16, g_f16);
    cudaGetSymbolAddress((void**)&p_g16, g_g16);
    cudaGetSymbolAddress((void**)&p_P, g_P);
    cudaGetSymbolAddress((void**)&p_S, g_S);
    cudaGetSymbolAddress((void**)&p_H, g_H);
    cudaGetSymbolAddress((void**)&p_abuf, g_abuf);
    cudaGetSymbolAddress((void**)&p_wbuf, g_wbuf);

    // weight layout: rows 0..6143 = [Wi|Wf|Wg], rows 6144..8191 = Wo
    __half* p_wifg = p_wbuf;
    __half* p_wo   = p_wbuf + (size_t)6144 * DD;

    cudaFuncSetAttribute((const void*)gemm_mma_kernel<__half, 1>,
                         cudaFuncAttributeMaxDynamicSharedMemorySize, GEMM_SMEM);
    cudaFuncSetAttribute((const void*)gemm_mma_kernel<float, 0>,
                         cudaFuncAttributeMaxDynamicSharedMemorySize, GEMM_SMEM);

    dim3 wgrid(DD / 32, DD / 32, 4), wblock(32, 8);
    convert_w_kernel<<<wgrid, wblock>>>(Wi, Wf, Wg, Wo, p_wbuf);
    convert_act_kernel<<<ELEMS / 1024, 256>>>(x, p_abuf);

    // fused i/f/g projections, K=2048, gate epilogue: si / a / swish(g)
    dim3 g3(48, MR / BM);
    gemm_mma_kernel<__half, 1><<<g3, 256, GEMM_SMEM>>>(p_abuf, p_wifg, p_i16, p_f16, p_g16);

    scan_pass1_kernel<<<(BSZ * NCH * D4) / 256, 256>>>(p_f16, p_i16, p_P, p_S);
    scan_pass2_kernel<<<(BSZ * DD) / 256, 256>>>(p_P, p_S, p_H);

    // fused pass3 + RMSNorm + swish-gate -> fp16 y (into abuf)
    scan3_norm_kernel<<<BSZ * NCH, 512>>>(p_f16, p_i16, p_H, p_g16, gw, p_abuf);

    // output projection, K=2048 fp16, fp32 output
    dim3 g1(16, MR / BM);
    gemm_mma_kernel<float, 0><<<g1, 256, GEMM_SMEM>>>(p_abuf, p_wo, out, out, out);
}

// round 17
// speedup vs baseline: 1.0367x; 1.0367x over previous
#include <cuda_runtime.h>
#include <cuda_fp16.h>
#include <math.h>
#include <stdint.h>

// Problem constants
#define BSZ 4
#define TT  4096
#define DD  2048
#define MR  (BSZ * TT)      // 16384 rows
#define MRH (MR / 2)        // 8192 rows per batch-half
#define LCH 32              // scan chunk length
#define NCH (TT / LCH)      // 128 chunks
#define ELEMS (MR * DD)
#define ELEMH (MRH * DD)

// ---------------- scratch (device globals; no allocation allowed) ----------
__device__ __half g_i16[ELEMS];                   // si = swish(i_raw)  fp16
__device__ __half g_f16[ELEMS];                   // a  = sigmoid(f_raw) fp16
__device__ __half g_g16[ELEMS];                   // gsw = swish(g_raw) fp16
__device__ __half g_obuf[ELEMS];                  // scan output fp16
__device__ float  g_P[BSZ * NCH * DD];
__device__ float  g_S[BSZ * NCH * DD];
__device__ float  g_H[BSZ * NCH * DD];
__device__ __half g_abuf[(size_t)MR * DD];        // fp16 activations (x, then y)
__device__ __half g_wbuf[(size_t)8192 * DD];      // [Wi|Wf|Wg|Wo] fp16, K-major

// =================== PTX helpers ===========================================
__device__ __forceinline__ uint32_t smem_u32(const void* p) {
    uint32_t a;
    asm("{ .reg .u64 t; cvta.to.shared.u64 t, %1; cvt.u32.u64 %0, t; }" : "=r"(a) : "l"(p));
    return a;
}
__device__ __forceinline__ void cp_async16(uint32_t dst, const void* src) {
    asm volatile("cp.async.cg.shared.global [%0], [%1], 16;" :: "r"(dst), "l"(src) : "memory");
}
__device__ __forceinline__ void cp_commit() {
    asm volatile("cp.async.commit_group;" ::: "memory");
}
template <int N>
__device__ __forceinline__ void cp_wait() {
    asm volatile("cp.async.wait_group %0;" :: "n"(N) : "memory");
}
__device__ __forceinline__ void ldm_x4(uint32_t* r, uint32_t addr) {
    asm volatile("ldmatrix.sync.aligned.m8n8.x4.shared.b16 {%0,%1,%2,%3}, [%4];"
        : "=r"(r[0]), "=r"(r[1]), "=r"(r[2]), "=r"(r[3]) : "r"(addr));
}
__device__ __forceinline__ void mma16816(float* c, const uint32_t* a, const uint32_t* b) {
    asm volatile("mma.sync.aligned.m16n8k16.row.col.f32.f16.f16.f32 "
        "{%0,%1,%2,%3}, {%4,%5,%6,%7}, {%8,%9}, {%0,%1,%2,%3};"
        : "+f"(c[0]), "+f"(c[1]), "+f"(c[2]), "+f"(c[3])
        : "r"(a[0]), "r"(a[1]), "r"(a[2]), "r"(a[3]), "r"(b[0]), "r"(b[1]));
}

// typed pair-stores for the GEMM epilogue
__device__ __forceinline__ void store2(float* p, float a, float b) {
    float2 v; v.x = a; v.y = b; *(float2*)p = v;
}
__device__ __forceinline__ void store2(__half* p, float a, float b) {
    __half2 v; v.x = __float2half(a); v.y = __float2half(b); *(__half2*)p = v;
}

// fp16x4 <-> fp32x4
__device__ __forceinline__ float4 h4_to_f4(uint2 v) {
    __half2 lo = *reinterpret_cast<__half2*>(&v.x);
    __half2 hi = *reinterpret_cast<__half2*>(&v.y);
    float2 f01 = __half22float2(lo);
    float2 f23 = __half22float2(hi);
    return make_float4(f01.x, f01.y, f23.x, f23.y);
}
__device__ __forceinline__ uint2 f4_to_h4(float4 v) {
    __half2 lo; lo.x = __float2half(v.x); lo.y = __float2half(v.y);
    __half2 hi; hi.x = __float2half(v.z); hi.y = __float2half(v.w);
    uint2 r;
    r.x = *reinterpret_cast<uint32_t*>(&lo);
    r.y = *reinterpret_cast<uint32_t*>(&hi);
    return r;
}

// fast sigmoid / swish (MUFU.RCP based)
__device__ __forceinline__ float fsig(float x) {
    return __fdividef(1.f, 1.f + __expf(-x));
}
__device__ __forceinline__ float fswish(float x) {
    return x * fsig(x);
}

// =================== conversions ===========================================
// activations: fp32 [M, 2048] -> plain fp16 [M, 2048]
__global__ __launch_bounds__(256)
void convert_act_kernel(const float* __restrict__ in, __half* __restrict__ out) {
    size_t idx = ((size_t)blockIdx.x * blockDim.x + threadIdx.x) * 4;
    float4 v = *(const float4*)(in + idx);
    __half2 h0; h0.x = __float2half(v.x); h0.y = __float2half(v.y);
    __half2 h1; h1.x = __float2half(v.z); h1.y = __float2half(v.w);
    *(__half2*)(out + idx) = h0;
    *(__half2*)(out + idx + 2) = h1;
}

// weights: fp32 W[k, n] -> fp16 Bo[n + 2048*z, 2048] K-major; one launch, z picks W
__global__ __launch_bounds__(256)
void convert_w_kernel(const float* __restrict__ W0, const float* __restrict__ W1,
                      const float* __restrict__ W2, const float* __restrict__ W3,
                      __half* __restrict__ Bo) {
    const float* Wsel[4] = {W0, W1, W2, W3};
    const float* W = Wsel[blockIdx.z];
    __half* B = Bo + (size_t)blockIdx.z * 2048 * DD;
    __shared__ float ts[32][33];
    int n0 = blockIdx.x * 32, k0 = blockIdx.y * 32;
    int tx = threadIdx.x, ty = threadIdx.y;  // (32, 8)
#pragma unroll
    for (int i = 0; i < 4; i++)
        ts[ty + i * 8][tx] = W[(size_t)(k0 + ty + i * 8) * DD + n0 + tx];
    __syncthreads();
#pragma unroll
    for (int i = 0; i < 4; i++) {
        int n = n0 + ty + i * 8;
        float v = ts[tx][ty + i * 8];     // = W[k0+tx][n]
        B[(size_t)n * DD + k0 + tx] = __float2half(v);
    }
}

// =================== mma.sync fp16 GEMM (R12 config — FROZEN mainloop) =====
// MODE 0: plain store. MODE 1: gate epilogue — which==1 stores sigmoid(acc),
// which==0/2 store swish(acc).
#define BM 128
#define BN 128
#define BKE 32
#define STAGE_A (BM * BKE * 2)              // 8192 B
#define STAGE_B (BN * BKE * 2)              // 8192 B
#define STAGE_BYTES (STAGE_A + STAGE_B)     // 16384
#define GEMM_SMEM (4 * STAGE_BYTES)         // 64 KB
#define KTILES (DD / BKE)                   // 64

// swizzled smem offset for a 16B chunk: row has 4 chunks (64B)
__device__ __forceinline__ uint32_t swz(int row, int ch) {
    return (uint32_t)(row * 64 + ((ch ^ ((row >> 1) & 3)) << 4));
}

template <typename TO, int MODE>
__global__ __launch_bounds__(256)
void gemm_mma_kernel(const __half* __restrict__ A, const __half* __restrict__ B,
                     TO* __restrict__ C0, TO* __restrict__ C1,
                     TO* __restrict__ C2) {
    extern __shared__ char smem[];
    const uint32_t sb = smem_u32(smem);
    const int tid = threadIdx.x;
    const int lane = tid & 31;
    const int wid = tid >> 5;
    const int wm = wid & 1;       // 2 warps over M: 64 rows each
    const int wn = wid >> 1;      // 4 warps over N: 32 cols each

    const __half* gA = A + (size_t)blockIdx.y * BM * DD;
    const __half* gB = B + (size_t)blockIdx.x * BN * DD;

    uint32_t aof[2][4], bof[2][2];
#pragma unroll
    for (int ks = 0; ks < 2; ks++) {
#pragma unroll
        for (int mf = 0; mf < 4; mf++) {
            int r = wm * 64 + mf * 16 + (lane & 15);
            int ch = ks * 2 + (lane >> 4);
            aof[ks][mf] = swz(r, ch);
        }
#pragma unroll
        for (int p = 0; p < 2; p++) {
            int r = wn * 32 + p * 16 + (lane & 7) + ((lane >> 4) << 3);
            int ch = ks * 2 + ((lane >> 3) & 1);
            bof[ks][p] = STAGE_A + swz(r, ch);
        }
    }

    float acc[4][4][4];
#pragma unroll
    for (int i = 0; i < 4; i++)
#pragma unroll
        for (int j = 0; j < 4; j++)
#pragma unroll
            for (int q = 0; q < 4; q++) acc[i][j][q] = 0.f;

    auto load_tile = [&](int kt) {
        uint32_t st = sb + (uint32_t)(kt & 3) * STAGE_BYTES;
        size_t koff = (size_t)kt * BKE;
#pragma unroll
        for (int h = 0; h < 2; h++) {
            int id = tid + h * 256;
            int row = id >> 2, ch = id & 3;
            cp_async16(st + swz(row, ch), gA + (size_t)row * DD + koff + ch * 8);
        }
#pragma unroll
        for (int h = 0; h < 2; h++) {
            int id = tid + h * 256;
            int row = id >> 2, ch = id & 3;
            cp_async16(st + STAGE_A + swz(row, ch), gB + (size_t)row * DD + koff + ch * 8);
        }
    };

    load_tile(0); cp_commit();
    load_tile(1); cp_commit();
    load_tile(2); cp_commit();

#pragma unroll 1
    for (int kt = 0; kt < KTILES; ++kt) {
        cp_wait<2>();
        __syncthreads();
        if (kt + 3 < KTILES) load_tile(kt + 3);
        cp_commit();

        uint32_t st = sb + (uint32_t)(kt & 3) * STAGE_BYTES;
#pragma unroll
        for (int ks = 0; ks < 2; ks++) {
            uint32_t ar[4][4], br[2][4];
#pragma unroll
            for (int mf = 0; mf < 4; mf++) ldm_x4(ar[mf], st + aof[ks][mf]);
#pragma unroll
            for (int p = 0; p < 2; p++) ldm_x4(br[p], st + bof[ks][p]);
#pragma unroll
            for (int mf = 0; mf < 4; mf++)
#pragma unroll
                for (int nf = 0; nf < 4; nf++)
                    mma16816(acc[mf][nf], ar[mf], &br[nf >> 1][(nf & 1) * 2]);
        }
    }

    // epilogue: pick output by weight block (blockIdx.x >> 4); optional gate
    int which = blockIdx.x >> 4;
    TO* Cb = (which == 0) ? C0 : (which == 1) ? C1 : C2;
    int colbase = (blockIdx.x & 15) * BN;
    auto actf = [&](float v) -> float {
        if (MODE == 0) return v;
        return (which == 1) ? fsig(v) : fswish(v);
    };
#pragma unroll
    for (int mf = 0; mf < 4; mf++) {
#pragma unroll
        for (int nf = 0; nf < 4; nf++) {
            int row = blockIdx.y * BM + wm * 64 + mf * 16 + (lane >> 2);
            int col = colbase + wn * 32 + nf * 8 + (lane & 3) * 2;
            store2(Cb + (size_t)row * DD + col, actf(acc[mf][nf][0]), actf(acc[mf][nf][1]));
            store2(Cb + (size_t)(row + 8) * DD + col, actf(acc[mf][nf][2]), actf(acc[mf][nf][3]));
        }
    }
}

// ---------------- chunked scan (gates precomputed; pure fma streaming) -----
// inputs: a = sigmoid(f_raw), si = swish(i_raw); i_t = si * (1 - a)
// All scan kernels operate on a HALF batch (2 sequences) via offset pointers.
#define D4 (DD / 4)
#define BSZH 2

__global__ void scan_pass1_kernel(const __half* __restrict__ ab, const __half* __restrict__ sib,
                                  float* __restrict__ P, float* __restrict__ S) {
    int idx = blockIdx.x * blockDim.x + threadIdx.x;   // over BSZH*NCH*D4
    int d4 = idx % D4;
    int c = (idx / D4) % NCH;
    int b = idx / (D4 * NCH);
    size_t base4 = (((size_t)(b * TT + c * LCH)) * DD) / 4 + d4;
    const uint2* a4 = (const uint2*)ab;
    const uint2* s4 = (const uint2*)sib;
    float4 h = make_float4(0.f, 0.f, 0.f, 0.f);
    float4 p = make_float4(1.f, 1.f, 1.f, 1.f);
#pragma unroll 4
    for (int j = 0; j < LCH; j++) {
        float4 a = h4_to_f4(a4[base4 + (size_t)j * D4]);
        float4 si = h4_to_f4(s4[base4 + (size_t)j * D4]);
        h.x = fmaf(a.x, h.x - si.x, si.x); p.x *= a.x;   // a*h + si*(1-a)
        h.y = fmaf(a.y, h.y - si.y, si.y); p.y *= a.y;
        h.z = fmaf(a.z, h.z - si.z, si.z); p.z *= a.z;
        h.w = fmaf(a.w, h.w - si.w, si.w); p.w *= a.w;
    }
    ((float4*)P)[idx] = p;
    ((float4*)S)[idx] = h;
}

// pass2: scalar, one thread per (b, d) column
__global__ void scan_pass2_kernel(const float* __restrict__ P, const float* __restrict__ S,
                                  float* __restrict__ H) {
    int idx = blockIdx.x * blockDim.x + threadIdx.x;   // over BSZH*DD
    int d = idx % DD;
    int b = idx / DD;
    float h = 0.f;
#pragma unroll 4
    for (int c = 0; c < NCH; c++) {
        int s = (b * NCH + c) * DD + d;
        H[s] = h;
        h = fmaf(P[s], h, S[s]);
    }
}

__global__ void scan_pass3_kernel(const __half* __restrict__ ab, const __half* __restrict__ sib,
                                  const float* __restrict__ H, __half* __restrict__ o) {
    int idx = blockIdx.x * blockDim.x + threadIdx.x;   // over BSZH*NCH*D4
    int d4 = idx % D4;
    int c = (idx / D4) % NCH;
    int b = idx / (D4 * NCH);
    size_t base4 = (((size_t)(b * TT + c * LCH)) * DD) / 4 + d4;
    const uint2* a4 = (const uint2*)ab;
    const uint2* s4 = (const uint2*)sib;
    uint2* o4 = (uint2*)o;
    float4 h = ((const float4*)H)[idx];
#pragma unroll 4
    for (int j = 0; j < LCH; j++) {
        float4 a = h4_to_f4(a4[base4 + (size_t)j * D4]);
        float4 si = h4_to_f4(s4[base4 + (size_t)j * D4]);
        h.x = fmaf(a.x, h.x - si.x, si.x);
        h.y = fmaf(a.y, h.y - si.y, si.y);
        h.z = fmaf(a.z, h.z - si.z, si.z);
        h.w = fmaf(a.w, h.w - si.w, si.w);
        o4[base4 + (size_t)j * D4] = f4_to_h4(h);
    }
}

// ---------------- RMSNorm + (pre-swished) gate + fp16 convert --------------
__global__ __launch_bounds__(256)
void norm_gate_convert_kernel(const __half* __restrict__ o, const __half* __restrict__ gsw,
                              const float* __restrict__ gw, __half* __restrict__ out) {
    int r = blockIdx.x;
    int tid = threadIdx.x;
    __shared__ float red[256];

    const uint2* orow = (const uint2*)(o + (size_t)r * DD);
    float4 vals[2];
    float ss = 0.f;
#pragma unroll
    for (int j = 0; j < 2; j++) {
        float4 v = h4_to_f4(orow[tid + j * 256]);
        vals[j] = v;
        ss = fmaf(v.x, v.x, ss);
        ss = fmaf(v.y, v.y, ss);
        ss = fmaf(v.z, v.z, ss);
        ss = fmaf(v.w, v.w, ss);
    }
    red[tid] = ss;
    __syncthreads();
    for (int s = 128; s > 0; s >>= 1) {
        if (tid < s) red[tid] += red[tid + s];
        __syncthreads();
    }
    float rinv = rsqrtf(red[0] / (float)DD + 1e-5f);

    const uint2* grow = (const uint2*)(gsw + (size_t)r * DD);
    const float4* gw4 = (const float4*)gw;
    __half* yrow = out + (size_t)r * DD;
#pragma unroll
    for (int j = 0; j < 2; j++) {
        int d4 = tid + j * 256;
        float4 gv = h4_to_f4(grow[d4]);
        float4 w = gw4[d4];
        float y0 = (vals[j].x * rinv * w.x) * gv.x;
        float y1 = (vals[j].y * rinv * w.y) * gv.y;
        float y2 = (vals[j].z * rinv * w.z) * gv.z;
        float y3 = (vals[j].w * rinv * w.w) * gv.w;
        __half2 hh0; hh0.x = __float2half(y0); hh0.y = __float2half(y1);
        __half2 hh1; hh1.x = __float2half(y2); hh1.y = __float2half(y3);
        int d = d4 * 4;
        *(__half2*)(yrow + d) = hh0;
        *(__half2*)(yrow + d + 2) = hh1;
    }
}

// ---------------- launch ----------------------------------------------------
extern "C" void kernel_launch(void* const* d_in, const int* in_sizes, int n_in,
                              void* d_out, int out_size) {
    const float* x  = (const float*)d_in[0];
    const float* Wi = (const float*)d_in[1];
    const float* Wf = (const float*)d_in[2];
    const float* Wg = (const float*)d_in[3];
    const float* Wo = (const float*)d_in[4];
    const float* gw = (const float*)d_in[5];
    float* out = (float*)d_out;

    float *p_P, *p_S, *p_H;
    __half *p_i16, *p_f16, *p_g16, *p_obuf, *p_abuf, *p_wbuf;
    cudaGetSymbolAddress((void**)&p_i16, g_i16);
    cudaGetSymbolAddress((void**)&p_f16, g_f16);
    cudaGetSymbolAddress((void**)&p_g16, g_g16);
    cudaGetSymbolAddress((void**)&p_obuf, g_obuf);
    cudaGetSymbolAddress((void**)&p_P, g_P);
    cudaGetSymbolAddress((void**)&p_S, g_S);
    cudaGetSymbolAddress((void**)&p_H, g_H);
    cudaGetSymbolAddress((void**)&p_abuf, g_abuf);
    cudaGetSymbolAddress((void**)&p_wbuf, g_wbuf);

    // weight layout: rows 0..6143 = [Wi|Wf|Wg], rows 6144..8191 = Wo
    __half* p_wifg = p_wbuf;
    __half* p_wo   = p_wbuf + (size_t)6144 * DD;

    cudaFuncSetAttribute((const void*)gemm_mma_kernel<__half, 1>,
                         cudaFuncAttributeMaxDynamicSharedMemorySize, GEMM_SMEM);
    cudaFuncSetAttribute((const void*)gemm_mma_kernel<float, 0>,
                         cudaFuncAttributeMaxDynamicSharedMemorySize, GEMM_SMEM);

    // one-time stream/event setup (host-side resources; launches below are
    // identical on every call, so work is deterministic)
    static cudaStream_t s1 = nullptr;
    static cudaEvent_t evF = nullptr, evJ = nullptr;
    if (s1 == nullptr) {
        cudaStreamCreateWithFlags(&s1, cudaStreamNonBlocking);
        cudaEventCreateWithFlags(&evF, cudaEventDisableTiming);
        cudaEventCreateWithFlags(&evJ, cudaEventDisableTiming);
    }

    // shared prologue on the main stream: weight conversion
    dim3 wgrid(DD / 32, DD / 32, 4), wblock(32, 8);
    convert_w_kernel<<<wgrid, wblock>>>(Wi, Wf, Wg, Wo, p_wbuf);

    // fork: stream s1 joins the capture after the weights are ready
    cudaEventRecord(evF, 0);
    cudaStreamWaitEvent(s1, evF, 0);

    const size_t PSH_H = (size_t)BSZH * NCH * DD;   // P/S/H elems per half
    dim3 g3(48, MRH / BM);   // (48, 64)
    dim3 g1(16, MRH / BM);   // (16, 64)

    for (int h = 0; h < 2; h++) {
        cudaStream_t st = (h == 0) ? (cudaStream_t)0 : s1;
        const size_t eo = (size_t)h * ELEMH;        // element offset for rows
        const size_t po = (size_t)h * PSH_H;

        convert_act_kernel<<<ELEMH / 1024, 256, 0, st>>>(x + eo, p_abuf + eo);

        gemm_mma_kernel<__half, 1><<<g3, 256, GEMM_SMEM, st>>>(
            p_abuf + eo, p_wifg, p_i16 + eo, p_f16 + eo, p_g16 + eo);

        scan_pass1_kernel<<<(BSZH * NCH * D4) / 256, 256, 0, st>>>(
            p_f16 + eo, p_i16 + eo, p_P + po, p_S + po);
        scan_pass2_kernel<<<(BSZH * DD) / 256, 256, 0, st>>>(
            p_P + po, p_S + po, p_H + po);
        scan_pass3_kernel<<<(BSZH * NCH * D4) / 256, 256, 0, st>>>(
            p_f16 + eo, p_i16 + eo, p_H + po, p_obuf + eo);

        norm_gate_convert_kernel<<<MRH, 256, 0, st>>>(
            p_obuf + eo, p_g16 + eo, gw, p_abuf + eo);

        gemm_mma_kernel<float, 0><<<g1, 256, GEMM_SMEM, st>>>(
            p_abuf + eo, p_wo, out + eo, out + eo, out + eo);
    }

    // join: main stream waits for s1's half before kernel_launch "completes"
    cudaEventRecord(evJ, s1);
    cudaStreamWaitEvent((cudaStream_t)0, evJ, 0);
}